// round 14
// baseline (speedup 1.0000x reference)
#include <cuda_runtime.h>
#include <cuda_bf16.h>

#define NN 100000
#define CC 64
#define EE 1200000
#define KD 32
#define HH 256

__device__ __nv_bfloat16 g_x1h[(size_t)NN * CC];  // conv accumulator (bf16)
__device__ __nv_bfloat16 g_xh[(size_t)NN * CC];   // x in bf16 for gathers

static __device__ __forceinline__ unsigned pk(float a, float b) {
    __nv_bfloat162 h = __floats2bfloat162_rn(a, b);
    return *reinterpret_cast<unsigned*>(&h);
}
static __device__ __forceinline__ unsigned hm2(unsigned a, unsigned b) {
    __nv_bfloat162 r = __hmul2(*reinterpret_cast<__nv_bfloat162*>(&a),
                               *reinterpret_cast<__nv_bfloat162*>(&b));
    return *reinterpret_cast<unsigned*>(&r);
}

static __device__ __forceinline__ void mma16816(
    float& d0, float& d1, float& d2, float& d3,
    unsigned a0, unsigned a1, unsigned a2, unsigned a3,
    unsigned b0, unsigned b1)
{
    asm volatile(
      "mma.sync.aligned.m16n8k16.row.col.f32.bf16.bf16.f32 "
      "{%0,%1,%2,%3}, {%4,%5,%6,%7}, {%8,%9}, {%0,%1,%2,%3};"
      : "+f"(d0), "+f"(d1), "+f"(d2), "+f"(d3)
      : "r"(a0), "r"(a1), "r"(a2), "r"(a3), "r"(b0), "r"(b1));
}

// ---------------------------------------------------------------------------
// Kernel 1: prep — convert x to bf16 and zero x1h
// ---------------------------------------------------------------------------
__global__ void prep_kernel(const float4* __restrict__ x4) {
    int i = blockIdx.x * blockDim.x + threadIdx.x;
    const int total = NN * CC / 4;
    uint2* xh2 = reinterpret_cast<uint2*>(g_xh);
    uint2* x12 = reinterpret_cast<uint2*>(g_x1h);
    for (; i < total; i += gridDim.x * blockDim.x) {
        float4 v = x4[i];
        xh2[i] = make_uint2(pk(v.x, v.y), pk(v.z, v.w));
        x12[i] = make_uint2(0u, 0u);
    }
}

// ---------------------------------------------------------------------------
// Kernel 2: edge pass (R10/R8 design — best measured). One warp = 32 edges/
// iter (2 HMMA tiles), batched loads; scatter balanced across all 32 lanes.
// sigma: D pair of group nt, lane t -> ch (nt>>1)*16 + 4t (+2 if nt odd).
// Grid widened to 1184 for finer tail balance.
// ---------------------------------------------------------------------------
__global__ void __launch_bounds__(256, 2) edge_kernel(
    const float* __restrict__ basis,
    const int* __restrict__ eidx,
    const float* __restrict__ W)
{
    const int lane = threadIdx.x & 31;
    const int t = lane & 3, g = lane >> 2;
    const int gwarp = (int)((blockIdx.x * blockDim.x + threadIdx.x) >> 5);
    const int nwarp = (int)((gridDim.x * blockDim.x) >> 5);

    unsigned bw[2][8][2];
#pragma unroll
    for (int kt = 0; kt < 2; kt++)
#pragma unroll
        for (int nt = 0; nt < 8; nt++) {
            int ch = (nt >> 1) * 16 + ((g >> 1) << 2) + (g & 1) + ((nt & 1) << 1);
            int col = kt * 16 + 2 * t;
            float2 p0 = *reinterpret_cast<const float2*>(W + ch * KD + col);
            float2 p1 = *reinterpret_cast<const float2*>(W + ch * KD + col + 8);
            bw[kt][nt][0] = pk(p0.x, p0.y);
            bw[kt][nt][1] = pk(p1.x, p1.y);
        }

    const uint2* xh2 = reinterpret_cast<const uint2*>(g_xh);
    const int NI = EE / 32;
    for (int it = gwarp; it < NI; it += nwarp) {
        const int e0 = it * 32;
        const int r0a = e0 + g,      r1a = e0 + 8 + g;
        const int r0b = e0 + 16 + g, r1b = e0 + 24 + g;
        const int s0a = __ldg(eidx + r0a), s1a = __ldg(eidx + r1a);
        const int s0b = __ldg(eidx + r0b), s1b = __ldg(eidx + r1b);
        const int d0a = __ldg(eidx + EE + r0a), d1a = __ldg(eidx + EE + r1a);
        const int d0b = __ldg(eidx + EE + r0b), d1b = __ldg(eidx + EE + r1b);

        unsigned Aa[2][4], Ab[2][4];
#pragma unroll
        for (int kt = 0; kt < 2; kt++) {
            const int cb = kt * 16 + 2 * t;
            float2 qa0 = *reinterpret_cast<const float2*>(basis + (size_t)r0a * KD + cb);
            float2 qa1 = *reinterpret_cast<const float2*>(basis + (size_t)r1a * KD + cb);
            float2 qa2 = *reinterpret_cast<const float2*>(basis + (size_t)r0a * KD + cb + 8);
            float2 qa3 = *reinterpret_cast<const float2*>(basis + (size_t)r1a * KD + cb + 8);
            float2 qb0 = *reinterpret_cast<const float2*>(basis + (size_t)r0b * KD + cb);
            float2 qb1 = *reinterpret_cast<const float2*>(basis + (size_t)r1b * KD + cb);
            float2 qb2 = *reinterpret_cast<const float2*>(basis + (size_t)r0b * KD + cb + 8);
            float2 qb3 = *reinterpret_cast<const float2*>(basis + (size_t)r1b * KD + cb + 8);
            Aa[kt][0] = pk(qa0.x, qa0.y); Aa[kt][1] = pk(qa1.x, qa1.y);
            Aa[kt][2] = pk(qa2.x, qa2.y); Aa[kt][3] = pk(qa3.x, qa3.y);
            Ab[kt][0] = pk(qb0.x, qb0.y); Ab[kt][1] = pk(qb1.x, qb1.y);
            Ab[kt][2] = pk(qb2.x, qb2.y); Ab[kt][3] = pk(qb3.x, qb3.y);
        }

        uint2 va0[4], va1[4], vb0[4], vb1[4];
#pragma unroll
        for (int ntp = 0; ntp < 4; ntp++) {
            va0[ntp] = xh2[(size_t)s0a * 16 + ntp * 4 + t];
            va1[ntp] = xh2[(size_t)s1a * 16 + ntp * 4 + t];
            vb0[ntp] = xh2[(size_t)s0b * 16 + ntp * 4 + t];
            vb1[ntp] = xh2[(size_t)s1b * 16 + ntp * 4 + t];
        }

#pragma unroll
        for (int tile = 0; tile < 2; tile++) {
            const unsigned (*A)[4] = tile ? Ab : Aa;
            const uint2* v0 = tile ? vb0 : va0;
            const uint2* v1 = tile ? vb1 : va1;
            const int dd0 = tile ? d0b : d0a;
            const int dd1 = tile ? d1b : d1a;
#pragma unroll
            for (int ntp = 0; ntp < 4; ntp++) {
                const int nt0 = 2 * ntp, nt1 = nt0 + 1;
                float D0[4] = {0.f, 0.f, 0.f, 0.f};
                float D1[4] = {0.f, 0.f, 0.f, 0.f};
#pragma unroll
                for (int kt = 0; kt < 2; kt++) {
                    mma16816(D0[0], D0[1], D0[2], D0[3],
                             A[kt][0], A[kt][1], A[kt][2], A[kt][3],
                             bw[kt][nt0][0], bw[kt][nt0][1]);
                    mma16816(D1[0], D1[1], D1[2], D1[3],
                             A[kt][0], A[kt][1], A[kt][2], A[kt][3],
                             bw[kt][nt1][0], bw[kt][nt1][1]);
                }
                unsigned q0x = hm2(pk(D0[0], D0[1]), v0[ntp].x);
                unsigned q0y = hm2(pk(D1[0], D1[1]), v0[ntp].y);
                unsigned q1x = hm2(pk(D0[2], D0[3]), v1[ntp].x);
                unsigned q1y = hm2(pk(D1[2], D1[3]), v1[ntp].y);
                unsigned p0x = __shfl_xor_sync(0xffffffffu, q0x, 1);
                unsigned p0y = __shfl_xor_sync(0xffffffffu, q0y, 1);
                unsigned p1x = __shfl_xor_sync(0xffffffffu, q1x, 1);
                unsigned p1y = __shfl_xor_sync(0xffffffffu, q1y, 1);
                if (!(t & 1)) {
                    __nv_bfloat16* a0 = g_x1h + (size_t)dd0 * CC + ntp * 16 + 4 * t;
                    asm volatile("red.global.add.noftz.v4.bf16x2 [%0], {%1,%2,%3,%4};"
                                 :: "l"(a0), "r"(q0x), "r"(q0y), "r"(p0x), "r"(p0y) : "memory");
                } else {
                    __nv_bfloat16* a1 = g_x1h + (size_t)dd1 * CC + ntp * 16 + 4 * (t - 1);
                    asm volatile("red.global.add.noftz.v4.bf16x2 [%0], {%1,%2,%3,%4};"
                                 :: "l"(a1), "r"(p1x), "r"(p1y), "r"(q1x), "r"(q1y) : "memory");
                }
            }
        }
    }
}

// ---------------------------------------------------------------------------
// Kernel 3: fused LN -> Lin(64->256) -> GELU -> Lin(256->64) -> ls*h + x.
// (R10 code; grid widened to 592 for finer tail balance)
// ---------------------------------------------------------------------------
__global__ void __launch_bounds__(256, 2) mlp_kernel(
    const float* __restrict__ x,
    const float* __restrict__ cbias,
    const float* __restrict__ gamma_,
    const float* __restrict__ beta_,
    const float* __restrict__ W1,
    const float* __restrict__ b1,
    const float* __restrict__ W2,
    const float* __restrict__ b2,
    const float* __restrict__ lscale,
    float* __restrict__ out)
{
    extern __shared__ unsigned char smraw[];
    uint2*  w1f = reinterpret_cast<uint2*>(smraw);
    uint2*  w2f = w1f + 4096;
    float2* b1p = reinterpret_cast<float2*>(w2f + 4096);
    float4* cbp4 = reinterpret_cast<float4*>(b1p + 1024);
    float4* gp4  = cbp4 + 128;
    float4* bp4  = gp4 + 128;
    float2* lsp = reinterpret_cast<float2*>(bp4 + 128);
    float2* lb2 = lsp + 256;

    const int tid = threadIdx.x;
    for (int i = tid; i < 4096; i += 256) {
        int kt = i >> 10, rem = i & 1023, ntg = rem >> 5, ln = rem & 31;
        int tt = ln & 3, gq = ln >> 2;
        int j = ntg * 8 + gq;
        float4 w = *reinterpret_cast<const float4*>(W1 + j * CC + kt * 16 + 4 * tt);
        w1f[i] = make_uint2(pk(w.x, w.y), pk(w.z, w.w));
    }
    for (int i = tid; i < 4096; i += 256) {
        int kt = i >> 8, rem = i & 255, nt = rem >> 5, ln = rem & 31;
        int tt = ln & 3, gq = ln >> 2;
        int c = nt * 8 + gq;
        int j = kt * 16 + 2 * tt;
        float2 p0 = *reinterpret_cast<const float2*>(W2 + c * HH + j);
        float2 p1 = *reinterpret_cast<const float2*>(W2 + c * HH + j + 8);
        w2f[i] = make_uint2(pk(p0.x, p0.y), pk(p1.x, p1.y));
    }
    for (int i = tid; i < 1024; i += 256) {
        int ch = i >> 8, rem = i & 255, nt = rem >> 5, ln = rem & 31, tt = ln & 3;
        int j = ch * 64 + nt * 8 + 2 * tt;
        b1p[i] = make_float2(b1[j], b1[j + 1]);
    }
    if (tid < 128) {
        int kt = tid >> 5, ln = tid & 31, tt = ln & 3;
        int c = kt * 16 + 4 * tt;
        cbp4[tid] = *reinterpret_cast<const float4*>(cbias + c);
        gp4[tid]  = *reinterpret_cast<const float4*>(gamma_ + c);
        bp4[tid]  = *reinterpret_cast<const float4*>(beta_ + c);
    }
    for (int i = tid; i < 256; i += 256) {
        int u = i >> 5, ln = i & 31, tt = ln & 3;
        int c = u * 8 + 2 * tt;
        float2 ls = *reinterpret_cast<const float2*>(lscale + c);
        float2 bb = *reinterpret_cast<const float2*>(b2 + c);
        lsp[i] = ls;
        lb2[i] = make_float2(ls.x * bb.x, ls.y * bb.y);
    }
    __syncthreads();

    const int lane = tid & 31, t = lane & 3, gq = lane >> 2;
    const int gwarp = (int)((blockIdx.x * 256 + tid) >> 5);
    const int nwarp = (int)(gridDim.x * 8);
    const uint2* x1h2 = reinterpret_cast<const uint2*>(g_x1h);
    const float2* xf2 = reinterpret_cast<const float2*>(x);
    float2* of2 = reinterpret_cast<float2*>(out);

    for (int grp = gwarp; grp < NN / 16; grp += nwarp) {
        const int row0 = grp * 16 + gq, row1 = row0 + 8;

        float a0[16], a1[16];
        float s0 = 0.f, q0 = 0.f, s1 = 0.f, q1 = 0.f;
#pragma unroll
        for (int kt = 0; kt < 4; kt++) {
            uint2 u0 = x1h2[(size_t)row0 * 16 + kt * 4 + t];
            uint2 u1 = x1h2[(size_t)row1 * 16 + kt * 4 + t];
            float4 cb = cbp4[kt * 32 + lane];
            float2 l0 = __bfloat1622float2(*reinterpret_cast<__nv_bfloat162*>(&u0.x));
            float2 h0 = __bfloat1622float2(*reinterpret_cast<__nv_bfloat162*>(&u0.y));
            float2 l1 = __bfloat1622float2(*reinterpret_cast<__nv_bfloat162*>(&u1.x));
            float2 h1 = __bfloat1622float2(*reinterpret_cast<__nv_bfloat162*>(&u1.y));
            a0[kt*4+0] = l0.x + cb.x; a0[kt*4+1] = l0.y + cb.y;
            a0[kt*4+2] = h0.x + cb.z; a0[kt*4+3] = h0.y + cb.w;
            a1[kt*4+0] = l1.x + cb.x; a1[kt*4+1] = l1.y + cb.y;
            a1[kt*4+2] = h1.x + cb.z; a1[kt*4+3] = h1.y + cb.w;
#pragma unroll
            for (int u = 0; u < 4; u++) {
                s0 += a0[kt*4+u]; q0 += a0[kt*4+u] * a0[kt*4+u];
                s1 += a1[kt*4+u]; q1 += a1[kt*4+u] * a1[kt*4+u];
            }
        }
#pragma unroll
        for (int o = 1; o <= 2; o <<= 1) {
            s0 += __shfl_xor_sync(0xffffffffu, s0, o);
            q0 += __shfl_xor_sync(0xffffffffu, q0, o);
            s1 += __shfl_xor_sync(0xffffffffu, s1, o);
            q1 += __shfl_xor_sync(0xffffffffu, q1, o);
        }
        float mu0 = s0 * (1.f / CC), mu1 = s1 * (1.f / CC);
        float rs0 = rsqrtf(q0 * (1.f / CC) - mu0 * mu0 + 1e-5f);
        float rs1 = rsqrtf(q1 * (1.f / CC) - mu1 * mu1 + 1e-5f);

        unsigned Afr[4][4];
#pragma unroll
        for (int kt = 0; kt < 4; kt++) {
            float4 gg = gp4[kt * 32 + lane], be = bp4[kt * 32 + lane];
            float n00 = (a0[kt*4+0] - mu0) * rs0 * gg.x + be.x;
            float n01 = (a0[kt*4+1] - mu0) * rs0 * gg.y + be.y;
            float n02 = (a0[kt*4+2] - mu0) * rs0 * gg.z + be.z;
            float n03 = (a0[kt*4+3] - mu0) * rs0 * gg.w + be.w;
            float n10 = (a1[kt*4+0] - mu1) * rs1 * gg.x + be.x;
            float n11 = (a1[kt*4+1] - mu1) * rs1 * gg.y + be.y;
            float n12 = (a1[kt*4+2] - mu1) * rs1 * gg.z + be.z;
            float n13 = (a1[kt*4+3] - mu1) * rs1 * gg.w + be.w;
            Afr[kt][0] = pk(n00, n01);
            Afr[kt][1] = pk(n10, n11);
            Afr[kt][2] = pk(n02, n03);
            Afr[kt][3] = pk(n12, n13);
        }

        float O[8][4];
#pragma unroll
        for (int nt = 0; nt < 8; nt++) { O[nt][0]=0.f; O[nt][1]=0.f; O[nt][2]=0.f; O[nt][3]=0.f; }

#pragma unroll
        for (int ch = 0; ch < 4; ch++) {
            float D1[8][4];
#pragma unroll
            for (int nt = 0; nt < 8; nt++) {
                float2 bb = b1p[(ch * 8 + nt) * 32 + lane];
                D1[nt][0] = bb.x; D1[nt][1] = bb.y; D1[nt][2] = bb.x; D1[nt][3] = bb.y;
            }
#pragma unroll
            for (int kt = 0; kt < 4; kt++) {
#pragma unroll
                for (int nt = 0; nt < 8; nt++) {
                    uint2 b = w1f[(kt * 32 + ch * 8 + nt) * 32 + lane];
                    mma16816(D1[nt][0], D1[nt][1], D1[nt][2], D1[nt][3],
                             Afr[kt][0], Afr[kt][1], Afr[kt][2], Afr[kt][3], b.x, b.y);
                }
            }
#pragma unroll
            for (int nt = 0; nt < 8; nt++)
#pragma unroll
                for (int r = 0; r < 4; r++) {
                    float a = D1[nt][r];
                    D1[nt][r] = a / (1.f + __expf(-1.702f * a));
                }
            unsigned Ap[4][4];
#pragma unroll
            for (int k2 = 0; k2 < 4; k2++) {
                Ap[k2][0] = pk(D1[2 * k2][0],     D1[2 * k2][1]);
                Ap[k2][1] = pk(D1[2 * k2][2],     D1[2 * k2][3]);
                Ap[k2][2] = pk(D1[2 * k2 + 1][0], D1[2 * k2 + 1][1]);
                Ap[k2][3] = pk(D1[2 * k2 + 1][2], D1[2 * k2 + 1][3]);
            }
#pragma unroll
            for (int k2 = 0; k2 < 4; k2++) {
                int ktg = ch * 4 + k2;
#pragma unroll
                for (int nt = 0; nt < 8; nt++) {
                    uint2 b = w2f[(ktg * 8 + nt) * 32 + lane];
                    mma16816(O[nt][0], O[nt][1], O[nt][2], O[nt][3],
                             Ap[k2][0], Ap[k2][1], Ap[k2][2], Ap[k2][3], b.x, b.y);
                }
            }
        }

#pragma unroll
        for (int nt = 0; nt < 8; nt++) {
            float2 ls = lsp[nt * 32 + lane];
            float2 lb = lb2[nt * 32 + lane];
            float2 xa = xf2[(size_t)row0 * 32 + nt * 4 + t];
            float2 xb = xf2[(size_t)row1 * 32 + nt * 4 + t];
            float2 ra, rb;
            ra.x = xa.x + lb.x + ls.x * O[nt][0];
            ra.y = xa.y + lb.y + ls.y * O[nt][1];
            rb.x = xb.x + lb.x + ls.x * O[nt][2];
            rb.y = xb.y + lb.y + ls.y * O[nt][3];
            of2[(size_t)row0 * 32 + nt * 4 + t] = ra;
            of2[(size_t)row1 * 32 + nt * 4 + t] = rb;
        }
    }
}

// ---------------------------------------------------------------------------
// launch  (inputs: 0 x, 1 kernel_basis, 2 fiber_kernel_basis, 3 edge_index
// (int32), 4 kernel_W, 5 conv_bias, 6 ln_gamma, 7 ln_beta, 8 W1, 9 b1,
// 10 W2, 11 b2, 12 layer_scale)
// ---------------------------------------------------------------------------
extern "C" void kernel_launch(void* const* d_in, const int* in_sizes, int n_in,
                              void* d_out, int out_size) {
    const float* x      = (const float*)d_in[0];
    const float* basis  = (const float*)d_in[1];
    const int*   eidx   = (const int*)d_in[3];
    const float* W      = (const float*)d_in[4];
    const float* cbias  = (const float*)d_in[5];
    const float* gamma_ = (const float*)d_in[6];
    const float* beta_  = (const float*)d_in[7];
    const float* W1     = (const float*)d_in[8];
    const float* b1     = (const float*)d_in[9];
    const float* W2     = (const float*)d_in[10];
    const float* b2     = (const float*)d_in[11];
    const float* lsc    = (const float*)d_in[12];
    float*       out    = (float*)d_out;

    prep_kernel<<<1184, 256>>>((const float4*)x);
    edge_kernel<<<1184, 256>>>(basis, eidx, W);

    const int smem = 32768 + 32768 + 8192 + 3 * 2048 + 2 * 2048;  // 83968 B
    cudaFuncSetAttribute(mlp_kernel, cudaFuncAttributeMaxDynamicSharedMemorySize, smem);
    mlp_kernel<<<592, 256, smem>>>(x, cbias, gamma_, beta_, W1, b1, W2, b2, lsc, out);
}

// round 15
// speedup vs baseline: 1.0939x; 1.0939x over previous
#include <cuda_runtime.h>
#include <cuda_bf16.h>

#define NN 100000
#define CC 64
#define EE 1200000
#define KD 32
#define HH 256

#define PREP_THREADS 320000          // 1250 blocks * 256
#define PREP_PER_THREAD 5            // 5 * 320000 = NN*CC/4 exactly

__device__ __nv_bfloat16 g_x1h[(size_t)NN * CC];  // conv accumulator (bf16)
__device__ __nv_bfloat16 g_xh[(size_t)NN * CC];   // x in bf16 for gathers

static __device__ __forceinline__ unsigned pk(float a, float b) {
    __nv_bfloat162 h = __floats2bfloat162_rn(a, b);
    return *reinterpret_cast<unsigned*>(&h);
}
static __device__ __forceinline__ unsigned hm2(unsigned a, unsigned b) {
    __nv_bfloat162 r = __hmul2(*reinterpret_cast<__nv_bfloat162*>(&a),
                               *reinterpret_cast<__nv_bfloat162*>(&b));
    return *reinterpret_cast<unsigned*>(&r);
}

static __device__ __forceinline__ void mma16816(
    float& d0, float& d1, float& d2, float& d3,
    unsigned a0, unsigned a1, unsigned a2, unsigned a3,
    unsigned b0, unsigned b1)
{
    asm volatile(
      "mma.sync.aligned.m16n8k16.row.col.f32.bf16.bf16.f32 "
      "{%0,%1,%2,%3}, {%4,%5,%6,%7}, {%8,%9}, {%0,%1,%2,%3};"
      : "+f"(d0), "+f"(d1), "+f"(d2), "+f"(d3)
      : "r"(a0), "r"(a1), "r"(a2), "r"(a3), "r"(b0), "r"(b1));
}

// ---------------------------------------------------------------------------
// Kernel 1: prep — convert x to bf16 and zero x1h. Exact-cover grid, 5
// strided elements per thread, loads batched first (MLP=5).
// ---------------------------------------------------------------------------
__global__ void __launch_bounds__(256) prep_kernel(const float4* __restrict__ x4) {
    const int tid = blockIdx.x * blockDim.x + threadIdx.x;
    uint2* xh2 = reinterpret_cast<uint2*>(g_xh);
    uint2* x12 = reinterpret_cast<uint2*>(g_x1h);
    float4 v[PREP_PER_THREAD];
#pragma unroll
    for (int k = 0; k < PREP_PER_THREAD; k++)
        v[k] = x4[tid + k * PREP_THREADS];
#pragma unroll
    for (int k = 0; k < PREP_PER_THREAD; k++) {
        int i = tid + k * PREP_THREADS;
        xh2[i] = make_uint2(pk(v[k].x, v[k].y), pk(v[k].z, v[k].w));
        x12[i] = make_uint2(0u, 0u);
    }
}

// ---------------------------------------------------------------------------
// Kernel 2: edge pass (R10/R8 design — best measured). One warp = 32 edges/
// iter (2 HMMA tiles), batched loads; scatter balanced across all 32 lanes.
// sigma: D pair of group nt, lane t -> ch (nt>>1)*16 + 4t (+2 if nt odd).
// ---------------------------------------------------------------------------
__global__ void __launch_bounds__(256, 2) edge_kernel(
    const float* __restrict__ basis,
    const int* __restrict__ eidx,
    const float* __restrict__ W)
{
    const int lane = threadIdx.x & 31;
    const int t = lane & 3, g = lane >> 2;
    const int gwarp = (int)((blockIdx.x * blockDim.x + threadIdx.x) >> 5);
    const int nwarp = (int)((gridDim.x * blockDim.x) >> 5);

    unsigned bw[2][8][2];
#pragma unroll
    for (int kt = 0; kt < 2; kt++)
#pragma unroll
        for (int nt = 0; nt < 8; nt++) {
            int ch = (nt >> 1) * 16 + ((g >> 1) << 2) + (g & 1) + ((nt & 1) << 1);
            int col = kt * 16 + 2 * t;
            float2 p0 = *reinterpret_cast<const float2*>(W + ch * KD + col);
            float2 p1 = *reinterpret_cast<const float2*>(W + ch * KD + col + 8);
            bw[kt][nt][0] = pk(p0.x, p0.y);
            bw[kt][nt][1] = pk(p1.x, p1.y);
        }

    const uint2* xh2 = reinterpret_cast<const uint2*>(g_xh);
    const int NI = EE / 32;
    for (int it = gwarp; it < NI; it += nwarp) {
        const int e0 = it * 32;
        const int r0a = e0 + g,      r1a = e0 + 8 + g;
        const int r0b = e0 + 16 + g, r1b = e0 + 24 + g;
        const int s0a = __ldg(eidx + r0a), s1a = __ldg(eidx + r1a);
        const int s0b = __ldg(eidx + r0b), s1b = __ldg(eidx + r1b);
        const int d0a = __ldg(eidx + EE + r0a), d1a = __ldg(eidx + EE + r1a);
        const int d0b = __ldg(eidx + EE + r0b), d1b = __ldg(eidx + EE + r1b);

        unsigned Aa[2][4], Ab[2][4];
#pragma unroll
        for (int kt = 0; kt < 2; kt++) {
            const int cb = kt * 16 + 2 * t;
            float2 qa0 = *reinterpret_cast<const float2*>(basis + (size_t)r0a * KD + cb);
            float2 qa1 = *reinterpret_cast<const float2*>(basis + (size_t)r1a * KD + cb);
            float2 qa2 = *reinterpret_cast<const float2*>(basis + (size_t)r0a * KD + cb + 8);
            float2 qa3 = *reinterpret_cast<const float2*>(basis + (size_t)r1a * KD + cb + 8);
            float2 qb0 = *reinterpret_cast<const float2*>(basis + (size_t)r0b * KD + cb);
            float2 qb1 = *reinterpret_cast<const float2*>(basis + (size_t)r1b * KD + cb);
            float2 qb2 = *reinterpret_cast<const float2*>(basis + (size_t)r0b * KD + cb + 8);
            float2 qb3 = *reinterpret_cast<const float2*>(basis + (size_t)r1b * KD + cb + 8);
            Aa[kt][0] = pk(qa0.x, qa0.y); Aa[kt][1] = pk(qa1.x, qa1.y);
            Aa[kt][2] = pk(qa2.x, qa2.y); Aa[kt][3] = pk(qa3.x, qa3.y);
            Ab[kt][0] = pk(qb0.x, qb0.y); Ab[kt][1] = pk(qb1.x, qb1.y);
            Ab[kt][2] = pk(qb2.x, qb2.y); Ab[kt][3] = pk(qb3.x, qb3.y);
        }

        uint2 va0[4], va1[4], vb0[4], vb1[4];
#pragma unroll
        for (int ntp = 0; ntp < 4; ntp++) {
            va0[ntp] = xh2[(size_t)s0a * 16 + ntp * 4 + t];
            va1[ntp] = xh2[(size_t)s1a * 16 + ntp * 4 + t];
            vb0[ntp] = xh2[(size_t)s0b * 16 + ntp * 4 + t];
            vb1[ntp] = xh2[(size_t)s1b * 16 + ntp * 4 + t];
        }

#pragma unroll
        for (int tile = 0; tile < 2; tile++) {
            const unsigned (*A)[4] = tile ? Ab : Aa;
            const uint2* v0 = tile ? vb0 : va0;
            const uint2* v1 = tile ? vb1 : va1;
            const int dd0 = tile ? d0b : d0a;
            const int dd1 = tile ? d1b : d1a;
#pragma unroll
            for (int ntp = 0; ntp < 4; ntp++) {
                const int nt0 = 2 * ntp, nt1 = nt0 + 1;
                float D0[4] = {0.f, 0.f, 0.f, 0.f};
                float D1[4] = {0.f, 0.f, 0.f, 0.f};
#pragma unroll
                for (int kt = 0; kt < 2; kt++) {
                    mma16816(D0[0], D0[1], D0[2], D0[3],
                             A[kt][0], A[kt][1], A[kt][2], A[kt][3],
                             bw[kt][nt0][0], bw[kt][nt0][1]);
                    mma16816(D1[0], D1[1], D1[2], D1[3],
                             A[kt][0], A[kt][1], A[kt][2], A[kt][3],
                             bw[kt][nt1][0], bw[kt][nt1][1]);
                }
                unsigned q0x = hm2(pk(D0[0], D0[1]), v0[ntp].x);
                unsigned q0y = hm2(pk(D1[0], D1[1]), v0[ntp].y);
                unsigned q1x = hm2(pk(D0[2], D0[3]), v1[ntp].x);
                unsigned q1y = hm2(pk(D1[2], D1[3]), v1[ntp].y);
                unsigned p0x = __shfl_xor_sync(0xffffffffu, q0x, 1);
                unsigned p0y = __shfl_xor_sync(0xffffffffu, q0y, 1);
                unsigned p1x = __shfl_xor_sync(0xffffffffu, q1x, 1);
                unsigned p1y = __shfl_xor_sync(0xffffffffu, q1y, 1);
                if (!(t & 1)) {
                    __nv_bfloat16* a0 = g_x1h + (size_t)dd0 * CC + ntp * 16 + 4 * t;
                    asm volatile("red.global.add.noftz.v4.bf16x2 [%0], {%1,%2,%3,%4};"
                                 :: "l"(a0), "r"(q0x), "r"(q0y), "r"(p0x), "r"(p0y) : "memory");
                } else {
                    __nv_bfloat16* a1 = g_x1h + (size_t)dd1 * CC + ntp * 16 + 4 * (t - 1);
                    asm volatile("red.global.add.noftz.v4.bf16x2 [%0], {%1,%2,%3,%4};"
                                 :: "l"(a1), "r"(p1x), "r"(p1y), "r"(q1x), "r"(q1y) : "memory");
                }
            }
        }
    }
}

// ---------------------------------------------------------------------------
// Kernel 3: fused LN -> Lin(64->256) -> GELU -> Lin(256->64) -> ls*h + x.
// (R10 code, grid 296 — measured best)
// ---------------------------------------------------------------------------
__global__ void __launch_bounds__(256, 2) mlp_kernel(
    const float* __restrict__ x,
    const float* __restrict__ cbias,
    const float* __restrict__ gamma_,
    const float* __restrict__ beta_,
    const float* __restrict__ W1,
    const float* __restrict__ b1,
    const float* __restrict__ W2,
    const float* __restrict__ b2,
    const float* __restrict__ lscale,
    float* __restrict__ out)
{
    extern __shared__ unsigned char smraw[];
    uint2*  w1f = reinterpret_cast<uint2*>(smraw);
    uint2*  w2f = w1f + 4096;
    float2* b1p = reinterpret_cast<float2*>(w2f + 4096);
    float4* cbp4 = reinterpret_cast<float4*>(b1p + 1024);
    float4* gp4  = cbp4 + 128;
    float4* bp4  = gp4 + 128;
    float2* lsp = reinterpret_cast<float2*>(bp4 + 128);
    float2* lb2 = lsp + 256;

    const int tid = threadIdx.x;
    for (int i = tid; i < 4096; i += 256) {
        int kt = i >> 10, rem = i & 1023, ntg = rem >> 5, ln = rem & 31;
        int tt = ln & 3, gq = ln >> 2;
        int j = ntg * 8 + gq;
        float4 w = *reinterpret_cast<const float4*>(W1 + j * CC + kt * 16 + 4 * tt);
        w1f[i] = make_uint2(pk(w.x, w.y), pk(w.z, w.w));
    }
    for (int i = tid; i < 4096; i += 256) {
        int kt = i >> 8, rem = i & 255, nt = rem >> 5, ln = rem & 31;
        int tt = ln & 3, gq = ln >> 2;
        int c = nt * 8 + gq;
        int j = kt * 16 + 2 * tt;
        float2 p0 = *reinterpret_cast<const float2*>(W2 + c * HH + j);
        float2 p1 = *reinterpret_cast<const float2*>(W2 + c * HH + j + 8);
        w2f[i] = make_uint2(pk(p0.x, p0.y), pk(p1.x, p1.y));
    }
    for (int i = tid; i < 1024; i += 256) {
        int ch = i >> 8, rem = i & 255, nt = rem >> 5, ln = rem & 31, tt = ln & 3;
        int j = ch * 64 + nt * 8 + 2 * tt;
        b1p[i] = make_float2(b1[j], b1[j + 1]);
    }
    if (tid < 128) {
        int kt = tid >> 5, ln = tid & 31, tt = ln & 3;
        int c = kt * 16 + 4 * tt;
        cbp4[tid] = *reinterpret_cast<const float4*>(cbias + c);
        gp4[tid]  = *reinterpret_cast<const float4*>(gamma_ + c);
        bp4[tid]  = *reinterpret_cast<const float4*>(beta_ + c);
    }
    for (int i = tid; i < 256; i += 256) {
        int u = i >> 5, ln = i & 31, tt = ln & 3;
        int c = u * 8 + 2 * tt;
        float2 ls = *reinterpret_cast<const float2*>(lscale + c);
        float2 bb = *reinterpret_cast<const float2*>(b2 + c);
        lsp[i] = ls;
        lb2[i] = make_float2(ls.x * bb.x, ls.y * bb.y);
    }
    __syncthreads();

    const int lane = tid & 31, t = lane & 3, gq = lane >> 2;
    const int gwarp = (int)((blockIdx.x * 256 + tid) >> 5);
    const int nwarp = (int)(gridDim.x * 8);
    const uint2* x1h2 = reinterpret_cast<const uint2*>(g_x1h);
    const float2* xf2 = reinterpret_cast<const float2*>(x);
    float2* of2 = reinterpret_cast<float2*>(out);

    for (int grp = gwarp; grp < NN / 16; grp += nwarp) {
        const int row0 = grp * 16 + gq, row1 = row0 + 8;

        float a0[16], a1[16];
        float s0 = 0.f, q0 = 0.f, s1 = 0.f, q1 = 0.f;
#pragma unroll
        for (int kt = 0; kt < 4; kt++) {
            uint2 u0 = x1h2[(size_t)row0 * 16 + kt * 4 + t];
            uint2 u1 = x1h2[(size_t)row1 * 16 + kt * 4 + t];
            float4 cb = cbp4[kt * 32 + lane];
            float2 l0 = __bfloat1622float2(*reinterpret_cast<__nv_bfloat162*>(&u0.x));
            float2 h0 = __bfloat1622float2(*reinterpret_cast<__nv_bfloat162*>(&u0.y));
            float2 l1 = __bfloat1622float2(*reinterpret_cast<__nv_bfloat162*>(&u1.x));
            float2 h1 = __bfloat1622float2(*reinterpret_cast<__nv_bfloat162*>(&u1.y));
            a0[kt*4+0] = l0.x + cb.x; a0[kt*4+1] = l0.y + cb.y;
            a0[kt*4+2] = h0.x + cb.z; a0[kt*4+3] = h0.y + cb.w;
            a1[kt*4+0] = l1.x + cb.x; a1[kt*4+1] = l1.y + cb.y;
            a1[kt*4+2] = h1.x + cb.z; a1[kt*4+3] = h1.y + cb.w;
#pragma unroll
            for (int u = 0; u < 4; u++) {
                s0 += a0[kt*4+u]; q0 += a0[kt*4+u] * a0[kt*4+u];
                s1 += a1[kt*4+u]; q1 += a1[kt*4+u] * a1[kt*4+u];
            }
        }
#pragma unroll
        for (int o = 1; o <= 2; o <<= 1) {
            s0 += __shfl_xor_sync(0xffffffffu, s0, o);
            q0 += __shfl_xor_sync(0xffffffffu, q0, o);
            s1 += __shfl_xor_sync(0xffffffffu, s1, o);
            q1 += __shfl_xor_sync(0xffffffffu, q1, o);
        }
        float mu0 = s0 * (1.f / CC), mu1 = s1 * (1.f / CC);
        float rs0 = rsqrtf(q0 * (1.f / CC) - mu0 * mu0 + 1e-5f);
        float rs1 = rsqrtf(q1 * (1.f / CC) - mu1 * mu1 + 1e-5f);

        unsigned Afr[4][4];
#pragma unroll
        for (int kt = 0; kt < 4; kt++) {
            float4 gg = gp4[kt * 32 + lane], be = bp4[kt * 32 + lane];
            float n00 = (a0[kt*4+0] - mu0) * rs0 * gg.x + be.x;
            float n01 = (a0[kt*4+1] - mu0) * rs0 * gg.y + be.y;
            float n02 = (a0[kt*4+2] - mu0) * rs0 * gg.z + be.z;
            float n03 = (a0[kt*4+3] - mu0) * rs0 * gg.w + be.w;
            float n10 = (a1[kt*4+0] - mu1) * rs1 * gg.x + be.x;
            float n11 = (a1[kt*4+1] - mu1) * rs1 * gg.y + be.y;
            float n12 = (a1[kt*4+2] - mu1) * rs1 * gg.z + be.z;
            float n13 = (a1[kt*4+3] - mu1) * rs1 * gg.w + be.w;
            Afr[kt][0] = pk(n00, n01);
            Afr[kt][1] = pk(n10, n11);
            Afr[kt][2] = pk(n02, n03);
            Afr[kt][3] = pk(n12, n13);
        }

        float O[8][4];
#pragma unroll
        for (int nt = 0; nt < 8; nt++) { O[nt][0]=0.f; O[nt][1]=0.f; O[nt][2]=0.f; O[nt][3]=0.f; }

#pragma unroll
        for (int ch = 0; ch < 4; ch++) {
            float D1[8][4];
#pragma unroll
            for (int nt = 0; nt < 8; nt++) {
                float2 bb = b1p[(ch * 8 + nt) * 32 + lane];
                D1[nt][0] = bb.x; D1[nt][1] = bb.y; D1[nt][2] = bb.x; D1[nt][3] = bb.y;
            }
#pragma unroll
            for (int kt = 0; kt < 4; kt++) {
#pragma unroll
                for (int nt = 0; nt < 8; nt++) {
                    uint2 b = w1f[(kt * 32 + ch * 8 + nt) * 32 + lane];
                    mma16816(D1[nt][0], D1[nt][1], D1[nt][2], D1[nt][3],
                             Afr[kt][0], Afr[kt][1], Afr[kt][2], Afr[kt][3], b.x, b.y);
                }
            }
#pragma unroll
            for (int nt = 0; nt < 8; nt++)
#pragma unroll
                for (int r = 0; r < 4; r++) {
                    float a = D1[nt][r];
                    D1[nt][r] = a / (1.f + __expf(-1.702f * a));
                }
            unsigned Ap[4][4];
#pragma unroll
            for (int k2 = 0; k2 < 4; k2++) {
                Ap[k2][0] = pk(D1[2 * k2][0],     D1[2 * k2][1]);
                Ap[k2][1] = pk(D1[2 * k2][2],     D1[2 * k2][3]);
                Ap[k2][2] = pk(D1[2 * k2 + 1][0], D1[2 * k2 + 1][1]);
                Ap[k2][3] = pk(D1[2 * k2 + 1][2], D1[2 * k2 + 1][3]);
            }
#pragma unroll
            for (int k2 = 0; k2 < 4; k2++) {
                int ktg = ch * 4 + k2;
#pragma unroll
                for (int nt = 0; nt < 8; nt++) {
                    uint2 b = w2f[(ktg * 8 + nt) * 32 + lane];
                    mma16816(O[nt][0], O[nt][1], O[nt][2], O[nt][3],
                             Ap[k2][0], Ap[k2][1], Ap[k2][2], Ap[k2][3], b.x, b.y);
                }
            }
        }

#pragma unroll
        for (int nt = 0; nt < 8; nt++) {
            float2 ls = lsp[nt * 32 + lane];
            float2 lb = lb2[nt * 32 + lane];
            float2 xa = xf2[(size_t)row0 * 32 + nt * 4 + t];
            float2 xb = xf2[(size_t)row1 * 32 + nt * 4 + t];
            float2 ra, rb;
            ra.x = xa.x + lb.x + ls.x * O[nt][0];
            ra.y = xa.y + lb.y + ls.y * O[nt][1];
            rb.x = xb.x + lb.x + ls.x * O[nt][2];
            rb.y = xb.y + lb.y + ls.y * O[nt][3];
            of2[(size_t)row0 * 32 + nt * 4 + t] = ra;
            of2[(size_t)row1 * 32 + nt * 4 + t] = rb;
        }
    }
}

// ---------------------------------------------------------------------------
// launch  (inputs: 0 x, 1 kernel_basis, 2 fiber_kernel_basis, 3 edge_index
// (int32), 4 kernel_W, 5 conv_bias, 6 ln_gamma, 7 ln_beta, 8 W1, 9 b1,
// 10 W2, 11 b2, 12 layer_scale)
// ---------------------------------------------------------------------------
extern "C" void kernel_launch(void* const* d_in, const int* in_sizes, int n_in,
                              void* d_out, int out_size) {
    const float* x      = (const float*)d_in[0];
    const float* basis  = (const float*)d_in[1];
    const int*   eidx   = (const int*)d_in[3];
    const float* W      = (const float*)d_in[4];
    const float* cbias  = (const float*)d_in[5];
    const float* gamma_ = (const float*)d_in[6];
    const float* beta_  = (const float*)d_in[7];
    const float* W1     = (const float*)d_in[8];
    const float* b1     = (const float*)d_in[9];
    const float* W2     = (const float*)d_in[10];
    const float* b2     = (const float*)d_in[11];
    const float* lsc    = (const float*)d_in[12];
    float*       out    = (float*)d_out;

    prep_kernel<<<1250, 256>>>((const float4*)x);
    edge_kernel<<<592, 256>>>(basis, eidx, W);

    const int smem = 32768 + 32768 + 8192 + 3 * 2048 + 2 * 2048;  // 83968 B
    cudaFuncSetAttribute(mlp_kernel, cudaFuncAttributeMaxDynamicSharedMemorySize, smem);
    mlp_kernel<<<296, 256, smem>>>(x, cbias, gamma_, beta_, W1, b1, W2, b2, lsc, out);
}

// round 16
// speedup vs baseline: 1.2048x; 1.1014x over previous
#include <cuda_runtime.h>
#include <cuda_bf16.h>

#define NN 100000
#define CC 64
#define EE 1200000
#define KD 32
#define HH 256

#define PREP_THREADS 320000          // 1250 blocks * 256
#define PREP_PER_THREAD 5            // 5 * 320000 = NN*CC/4 exactly

__device__ __nv_bfloat16 g_x1h[(size_t)NN * CC];  // conv accumulator (bf16)
__device__ __nv_bfloat16 g_xh[(size_t)NN * CC];   // x in bf16 for gathers

static __device__ __forceinline__ unsigned pk(float a, float b) {
    __nv_bfloat162 h = __floats2bfloat162_rn(a, b);
    return *reinterpret_cast<unsigned*>(&h);
}
static __device__ __forceinline__ unsigned hm2(unsigned a, unsigned b) {
    __nv_bfloat162 r = __hmul2(*reinterpret_cast<__nv_bfloat162*>(&a),
                               *reinterpret_cast<__nv_bfloat162*>(&b));
    return *reinterpret_cast<unsigned*>(&r);
}

static __device__ __forceinline__ void mma16816(
    float& d0, float& d1, float& d2, float& d3,
    unsigned a0, unsigned a1, unsigned a2, unsigned a3,
    unsigned b0, unsigned b1)
{
    asm volatile(
      "mma.sync.aligned.m16n8k16.row.col.f32.bf16.bf16.f32 "
      "{%0,%1,%2,%3}, {%4,%5,%6,%7}, {%8,%9}, {%0,%1,%2,%3};"
      : "+f"(d0), "+f"(d1), "+f"(d2), "+f"(d3)
      : "r"(a0), "r"(a1), "r"(a2), "r"(a3), "r"(b0), "r"(b1));
}

// ---------------------------------------------------------------------------
// Kernel 1: prep — convert x to bf16 and zero x1h. Exact-cover grid, 5
// strided elements per thread, loads batched first (MLP=5).
// ---------------------------------------------------------------------------
__global__ void __launch_bounds__(256) prep_kernel(const float4* __restrict__ x4) {
    const int tid = blockIdx.x * blockDim.x + threadIdx.x;
    uint2* xh2 = reinterpret_cast<uint2*>(g_xh);
    uint2* x12 = reinterpret_cast<uint2*>(g_x1h);
    float4 v[PREP_PER_THREAD];
#pragma unroll
    for (int k = 0; k < PREP_PER_THREAD; k++)
        v[k] = x4[tid + k * PREP_THREADS];
#pragma unroll
    for (int k = 0; k < PREP_PER_THREAD; k++) {
        int i = tid + k * PREP_THREADS;
        xh2[i] = make_uint2(pk(v[k].x, v[k].y), pk(v[k].z, v[k].w));
        x12[i] = make_uint2(0u, 0u);
    }
}

// ---------------------------------------------------------------------------
// Kernel 2: edge pass (R10/R8 design — best measured). One warp = 32 edges/
// iter (2 HMMA tiles), batched loads; scatter balanced across all 32 lanes.
// sigma: D pair of group nt, lane t -> ch (nt>>1)*16 + 4t (+2 if nt odd).
// ---------------------------------------------------------------------------
__global__ void __launch_bounds__(256, 2) edge_kernel(
    const float* __restrict__ basis,
    const int* __restrict__ eidx,
    const float* __restrict__ W)
{
    const int lane = threadIdx.x & 31;
    const int t = lane & 3, g = lane >> 2;
    const int gwarp = (int)((blockIdx.x * blockDim.x + threadIdx.x) >> 5);
    const int nwarp = (int)((gridDim.x * blockDim.x) >> 5);

    unsigned bw[2][8][2];
#pragma unroll
    for (int kt = 0; kt < 2; kt++)
#pragma unroll
        for (int nt = 0; nt < 8; nt++) {
            int ch = (nt >> 1) * 16 + ((g >> 1) << 2) + (g & 1) + ((nt & 1) << 1);
            int col = kt * 16 + 2 * t;
            float2 p0 = *reinterpret_cast<const float2*>(W + ch * KD + col);
            float2 p1 = *reinterpret_cast<const float2*>(W + ch * KD + col + 8);
            bw[kt][nt][0] = pk(p0.x, p0.y);
            bw[kt][nt][1] = pk(p1.x, p1.y);
        }

    const uint2* xh2 = reinterpret_cast<const uint2*>(g_xh);
    const int NI = EE / 32;
    for (int it = gwarp; it < NI; it += nwarp) {
        const int e0 = it * 32;
        const int r0a = e0 + g,      r1a = e0 + 8 + g;
        const int r0b = e0 + 16 + g, r1b = e0 + 24 + g;
        const int s0a = __ldg(eidx + r0a), s1a = __ldg(eidx + r1a);
        const int s0b = __ldg(eidx + r0b), s1b = __ldg(eidx + r1b);
        const int d0a = __ldg(eidx + EE + r0a), d1a = __ldg(eidx + EE + r1a);
        const int d0b = __ldg(eidx + EE + r0b), d1b = __ldg(eidx + EE + r1b);

        unsigned Aa[2][4], Ab[2][4];
#pragma unroll
        for (int kt = 0; kt < 2; kt++) {
            const int cb = kt * 16 + 2 * t;
            float2 qa0 = *reinterpret_cast<const float2*>(basis + (size_t)r0a * KD + cb);
            float2 qa1 = *reinterpret_cast<const float2*>(basis + (size_t)r1a * KD + cb);
            float2 qa2 = *reinterpret_cast<const float2*>(basis + (size_t)r0a * KD + cb + 8);
            float2 qa3 = *reinterpret_cast<const float2*>(basis + (size_t)r1a * KD + cb + 8);
            float2 qb0 = *reinterpret_cast<const float2*>(basis + (size_t)r0b * KD + cb);
            float2 qb1 = *reinterpret_cast<const float2*>(basis + (size_t)r1b * KD + cb);
            float2 qb2 = *reinterpret_cast<const float2*>(basis + (size_t)r0b * KD + cb + 8);
            float2 qb3 = *reinterpret_cast<const float2*>(basis + (size_t)r1b * KD + cb + 8);
            Aa[kt][0] = pk(qa0.x, qa0.y); Aa[kt][1] = pk(qa1.x, qa1.y);
            Aa[kt][2] = pk(qa2.x, qa2.y); Aa[kt][3] = pk(qa3.x, qa3.y);
            Ab[kt][0] = pk(qb0.x, qb0.y); Ab[kt][1] = pk(qb1.x, qb1.y);
            Ab[kt][2] = pk(qb2.x, qb2.y); Ab[kt][3] = pk(qb3.x, qb3.y);
        }

        uint2 va0[4], va1[4], vb0[4], vb1[4];
#pragma unroll
        for (int ntp = 0; ntp < 4; ntp++) {
            va0[ntp] = xh2[(size_t)s0a * 16 + ntp * 4 + t];
            va1[ntp] = xh2[(size_t)s1a * 16 + ntp * 4 + t];
            vb0[ntp] = xh2[(size_t)s0b * 16 + ntp * 4 + t];
            vb1[ntp] = xh2[(size_t)s1b * 16 + ntp * 4 + t];
        }

#pragma unroll
        for (int tile = 0; tile < 2; tile++) {
            const unsigned (*A)[4] = tile ? Ab : Aa;
            const uint2* v0 = tile ? vb0 : va0;
            const uint2* v1 = tile ? vb1 : va1;
            const int dd0 = tile ? d0b : d0a;
            const int dd1 = tile ? d1b : d1a;
#pragma unroll
            for (int ntp = 0; ntp < 4; ntp++) {
                const int nt0 = 2 * ntp, nt1 = nt0 + 1;
                float D0[4] = {0.f, 0.f, 0.f, 0.f};
                float D1[4] = {0.f, 0.f, 0.f, 0.f};
#pragma unroll
                for (int kt = 0; kt < 2; kt++) {
                    mma16816(D0[0], D0[1], D0[2], D0[3],
                             A[kt][0], A[kt][1], A[kt][2], A[kt][3],
                             bw[kt][nt0][0], bw[kt][nt0][1]);
                    mma16816(D1[0], D1[1], D1[2], D1[3],
                             A[kt][0], A[kt][1], A[kt][2], A[kt][3],
                             bw[kt][nt1][0], bw[kt][nt1][1]);
                }
                unsigned q0x = hm2(pk(D0[0], D0[1]), v0[ntp].x);
                unsigned q0y = hm2(pk(D1[0], D1[1]), v0[ntp].y);
                unsigned q1x = hm2(pk(D0[2], D0[3]), v1[ntp].x);
                unsigned q1y = hm2(pk(D1[2], D1[3]), v1[ntp].y);
                unsigned p0x = __shfl_xor_sync(0xffffffffu, q0x, 1);
                unsigned p0y = __shfl_xor_sync(0xffffffffu, q0y, 1);
                unsigned p1x = __shfl_xor_sync(0xffffffffu, q1x, 1);
                unsigned p1y = __shfl_xor_sync(0xffffffffu, q1y, 1);
                if (!(t & 1)) {
                    __nv_bfloat16* a0 = g_x1h + (size_t)dd0 * CC + ntp * 16 + 4 * t;
                    asm volatile("red.global.add.noftz.v4.bf16x2 [%0], {%1,%2,%3,%4};"
                                 :: "l"(a0), "r"(q0x), "r"(q0y), "r"(p0x), "r"(p0y) : "memory");
                } else {
                    __nv_bfloat16* a1 = g_x1h + (size_t)dd1 * CC + ntp * 16 + 4 * (t - 1);
                    asm volatile("red.global.add.noftz.v4.bf16x2 [%0], {%1,%2,%3,%4};"
                                 :: "l"(a1), "r"(p1x), "r"(p1y), "r"(q1x), "r"(q1y) : "memory");
                }
            }
        }
    }
}

// ---------------------------------------------------------------------------
// Kernel 3: fused LN -> Lin(64->256) -> GELU -> Lin(256->64) -> ls*h + x.
// (R10 code; GELU division replaced with __fdividef — MUFU.RCP path)
// ---------------------------------------------------------------------------
__global__ void __launch_bounds__(256, 2) mlp_kernel(
    const float* __restrict__ x,
    const float* __restrict__ cbias,
    const float* __restrict__ gamma_,
    const float* __restrict__ beta_,
    const float* __restrict__ W1,
    const float* __restrict__ b1,
    const float* __restrict__ W2,
    const float* __restrict__ b2,
    const float* __restrict__ lscale,
    float* __restrict__ out)
{
    extern __shared__ unsigned char smraw[];
    uint2*  w1f = reinterpret_cast<uint2*>(smraw);
    uint2*  w2f = w1f + 4096;
    float2* b1p = reinterpret_cast<float2*>(w2f + 4096);
    float4* cbp4 = reinterpret_cast<float4*>(b1p + 1024);
    float4* gp4  = cbp4 + 128;
    float4* bp4  = gp4 + 128;
    float2* lsp = reinterpret_cast<float2*>(bp4 + 128);
    float2* lb2 = lsp + 256;

    const int tid = threadIdx.x;
    for (int i = tid; i < 4096; i += 256) {
        int kt = i >> 10, rem = i & 1023, ntg = rem >> 5, ln = rem & 31;
        int tt = ln & 3, gq = ln >> 2;
        int j = ntg * 8 + gq;
        float4 w = *reinterpret_cast<const float4*>(W1 + j * CC + kt * 16 + 4 * tt);
        w1f[i] = make_uint2(pk(w.x, w.y), pk(w.z, w.w));
    }
    for (int i = tid; i < 4096; i += 256) {
        int kt = i >> 8, rem = i & 255, nt = rem >> 5, ln = rem & 31;
        int tt = ln & 3, gq = ln >> 2;
        int c = nt * 8 + gq;
        int j = kt * 16 + 2 * tt;
        float2 p0 = *reinterpret_cast<const float2*>(W2 + c * HH + j);
        float2 p1 = *reinterpret_cast<const float2*>(W2 + c * HH + j + 8);
        w2f[i] = make_uint2(pk(p0.x, p0.y), pk(p1.x, p1.y));
    }
    for (int i = tid; i < 1024; i += 256) {
        int ch = i >> 8, rem = i & 255, nt = rem >> 5, ln = rem & 31, tt = ln & 3;
        int j = ch * 64 + nt * 8 + 2 * tt;
        b1p[i] = make_float2(b1[j], b1[j + 1]);
    }
    if (tid < 128) {
        int kt = tid >> 5, ln = tid & 31, tt = ln & 3;
        int c = kt * 16 + 4 * tt;
        cbp4[tid] = *reinterpret_cast<const float4*>(cbias + c);
        gp4[tid]  = *reinterpret_cast<const float4*>(gamma_ + c);
        bp4[tid]  = *reinterpret_cast<const float4*>(beta_ + c);
    }
    for (int i = tid; i < 256; i += 256) {
        int u = i >> 5, ln = i & 31, tt = ln & 3;
        int c = u * 8 + 2 * tt;
        float2 ls = *reinterpret_cast<const float2*>(lscale + c);
        float2 bb = *reinterpret_cast<const float2*>(b2 + c);
        lsp[i] = ls;
        lb2[i] = make_float2(ls.x * bb.x, ls.y * bb.y);
    }
    __syncthreads();

    const int lane = tid & 31, t = lane & 3, gq = lane >> 2;
    const int gwarp = (int)((blockIdx.x * 256 + tid) >> 5);
    const int nwarp = (int)(gridDim.x * 8);
    const uint2* x1h2 = reinterpret_cast<const uint2*>(g_x1h);
    const float2* xf2 = reinterpret_cast<const float2*>(x);
    float2* of2 = reinterpret_cast<float2*>(out);

    for (int grp = gwarp; grp < NN / 16; grp += nwarp) {
        const int row0 = grp * 16 + gq, row1 = row0 + 8;

        float a0[16], a1[16];
        float s0 = 0.f, q0 = 0.f, s1 = 0.f, q1 = 0.f;
#pragma unroll
        for (int kt = 0; kt < 4; kt++) {
            uint2 u0 = x1h2[(size_t)row0 * 16 + kt * 4 + t];
            uint2 u1 = x1h2[(size_t)row1 * 16 + kt * 4 + t];
            float4 cb = cbp4[kt * 32 + lane];
            float2 l0 = __bfloat1622float2(*reinterpret_cast<__nv_bfloat162*>(&u0.x));
            float2 h0 = __bfloat1622float2(*reinterpret_cast<__nv_bfloat162*>(&u0.y));
            float2 l1 = __bfloat1622float2(*reinterpret_cast<__nv_bfloat162*>(&u1.x));
            float2 h1 = __bfloat1622float2(*reinterpret_cast<__nv_bfloat162*>(&u1.y));
            a0[kt*4+0] = l0.x + cb.x; a0[kt*4+1] = l0.y + cb.y;
            a0[kt*4+2] = h0.x + cb.z; a0[kt*4+3] = h0.y + cb.w;
            a1[kt*4+0] = l1.x + cb.x; a1[kt*4+1] = l1.y + cb.y;
            a1[kt*4+2] = h1.x + cb.z; a1[kt*4+3] = h1.y + cb.w;
#pragma unroll
            for (int u = 0; u < 4; u++) {
                s0 += a0[kt*4+u]; q0 += a0[kt*4+u] * a0[kt*4+u];
                s1 += a1[kt*4+u]; q1 += a1[kt*4+u] * a1[kt*4+u];
            }
        }
#pragma unroll
        for (int o = 1; o <= 2; o <<= 1) {
            s0 += __shfl_xor_sync(0xffffffffu, s0, o);
            q0 += __shfl_xor_sync(0xffffffffu, q0, o);
            s1 += __shfl_xor_sync(0xffffffffu, s1, o);
            q1 += __shfl_xor_sync(0xffffffffu, q1, o);
        }
        float mu0 = s0 * (1.f / CC), mu1 = s1 * (1.f / CC);
        float rs0 = rsqrtf(q0 * (1.f / CC) - mu0 * mu0 + 1e-5f);
        float rs1 = rsqrtf(q1 * (1.f / CC) - mu1 * mu1 + 1e-5f);

        unsigned Afr[4][4];
#pragma unroll
        for (int kt = 0; kt < 4; kt++) {
            float4 gg = gp4[kt * 32 + lane], be = bp4[kt * 32 + lane];
            float n00 = (a0[kt*4+0] - mu0) * rs0 * gg.x + be.x;
            float n01 = (a0[kt*4+1] - mu0) * rs0 * gg.y + be.y;
            float n02 = (a0[kt*4+2] - mu0) * rs0 * gg.z + be.z;
            float n03 = (a0[kt*4+3] - mu0) * rs0 * gg.w + be.w;
            float n10 = (a1[kt*4+0] - mu1) * rs1 * gg.x + be.x;
            float n11 = (a1[kt*4+1] - mu1) * rs1 * gg.y + be.y;
            float n12 = (a1[kt*4+2] - mu1) * rs1 * gg.z + be.z;
            float n13 = (a1[kt*4+3] - mu1) * rs1 * gg.w + be.w;
            Afr[kt][0] = pk(n00, n01);
            Afr[kt][1] = pk(n10, n11);
            Afr[kt][2] = pk(n02, n03);
            Afr[kt][3] = pk(n12, n13);
        }

        float O[8][4];
#pragma unroll
        for (int nt = 0; nt < 8; nt++) { O[nt][0]=0.f; O[nt][1]=0.f; O[nt][2]=0.f; O[nt][3]=0.f; }

#pragma unroll
        for (int ch = 0; ch < 4; ch++) {
            float D1[8][4];
#pragma unroll
            for (int nt = 0; nt < 8; nt++) {
                float2 bb = b1p[(ch * 8 + nt) * 32 + lane];
                D1[nt][0] = bb.x; D1[nt][1] = bb.y; D1[nt][2] = bb.x; D1[nt][3] = bb.y;
            }
#pragma unroll
            for (int kt = 0; kt < 4; kt++) {
#pragma unroll
                for (int nt = 0; nt < 8; nt++) {
                    uint2 b = w1f[(kt * 32 + ch * 8 + nt) * 32 + lane];
                    mma16816(D1[nt][0], D1[nt][1], D1[nt][2], D1[nt][3],
                             Afr[kt][0], Afr[kt][1], Afr[kt][2], Afr[kt][3], b.x, b.y);
                }
            }
            // GELU (sigmoid approx, fast division — error suppressed by layer_scale)
#pragma unroll
            for (int nt = 0; nt < 8; nt++)
#pragma unroll
                for (int r = 0; r < 4; r++) {
                    float a = D1[nt][r];
                    D1[nt][r] = __fdividef(a, 1.f + __expf(-1.702f * a));
                }
            unsigned Ap[4][4];
#pragma unroll
            for (int k2 = 0; k2 < 4; k2++) {
                Ap[k2][0] = pk(D1[2 * k2][0],     D1[2 * k2][1]);
                Ap[k2][1] = pk(D1[2 * k2][2],     D1[2 * k2][3]);
                Ap[k2][2] = pk(D1[2 * k2 + 1][0], D1[2 * k2 + 1][1]);
                Ap[k2][3] = pk(D1[2 * k2 + 1][2], D1[2 * k2 + 1][3]);
            }
#pragma unroll
            for (int k2 = 0; k2 < 4; k2++) {
                int ktg = ch * 4 + k2;
#pragma unroll
                for (int nt = 0; nt < 8; nt++) {
                    uint2 b = w2f[(ktg * 8 + nt) * 32 + lane];
                    mma16816(O[nt][0], O[nt][1], O[nt][2], O[nt][3],
                             Ap[k2][0], Ap[k2][1], Ap[k2][2], Ap[k2][3], b.x, b.y);
                }
            }
        }

#pragma unroll
        for (int nt = 0; nt < 8; nt++) {
            float2 ls = lsp[nt * 32 + lane];
            float2 lb = lb2[nt * 32 + lane];
            float2 xa = xf2[(size_t)row0 * 32 + nt * 4 + t];
            float2 xb = xf2[(size_t)row1 * 32 + nt * 4 + t];
            float2 ra, rb;
            ra.x = xa.x + lb.x + ls.x * O[nt][0];
            ra.y = xa.y + lb.y + ls.y * O[nt][1];
            rb.x = xb.x + lb.x + ls.x * O[nt][2];
            rb.y = xb.y + lb.y + ls.y * O[nt][3];
            of2[(size_t)row0 * 32 + nt * 4 + t] = ra;
            of2[(size_t)row1 * 32 + nt * 4 + t] = rb;
        }
    }
}

// ---------------------------------------------------------------------------
// launch  (inputs: 0 x, 1 kernel_basis, 2 fiber_kernel_basis, 3 edge_index
// (int32), 4 kernel_W, 5 conv_bias, 6 ln_gamma, 7 ln_beta, 8 W1, 9 b1,
// 10 W2, 11 b2, 12 layer_scale)
// ---------------------------------------------------------------------------
extern "C" void kernel_launch(void* const* d_in, const int* in_sizes, int n_in,
                              void* d_out, int out_size) {
    const float* x      = (const float*)d_in[0];
    const float* basis  = (const float*)d_in[1];
    const int*   eidx   = (const int*)d_in[3];
    const float* W      = (const float*)d_in[4];
    const float* cbias  = (const float*)d_in[5];
    const float* gamma_ = (const float*)d_in[6];
    const float* beta_  = (const float*)d_in[7];
    const float* W1     = (const float*)d_in[8];
    const float* b1     = (const float*)d_in[9];
    const float* W2     = (const float*)d_in[10];
    const float* b2     = (const float*)d_in[11];
    const float* lsc    = (const float*)d_in[12];
    float*       out    = (float*)d_out;

    prep_kernel<<<1250, 256>>>((const float4*)x);
    edge_kernel<<<592, 256>>>(basis, eidx, W);

    const int smem = 32768 + 32768 + 8192 + 3 * 2048 + 2 * 2048;  // 83968 B
    cudaFuncSetAttribute(mlp_kernel, cudaFuncAttributeMaxDynamicSharedMemorySize, smem);
    mlp_kernel<<<296, 256, smem>>>(x, cbias, gamma_, beta_, W1, b1, W2, b2, lsc, out);
}

// round 17
// speedup vs baseline: 1.2374x; 1.0270x over previous
#include <cuda_runtime.h>
#include <cuda_bf16.h>

#define NN 100000
#define CC 64
#define EE 1200000
#define KD 32
#define HH 256

#define PREP_THREADS 320000          // 1250 blocks * 256
#define PREP_PER_THREAD 5            // 5 * 320000 = NN*CC/4 exactly

__device__ __nv_bfloat16 g_x1h[(size_t)NN * CC];  // conv accumulator (bf16)
__device__ __nv_bfloat16 g_xh[(size_t)NN * CC];   // x in bf16 for gathers

static __device__ __forceinline__ unsigned pk(float a, float b) {
    __nv_bfloat162 h = __floats2bfloat162_rn(a, b);
    return *reinterpret_cast<unsigned*>(&h);
}
static __device__ __forceinline__ unsigned hm2(unsigned a, unsigned b) {
    __nv_bfloat162 r = __hmul2(*reinterpret_cast<__nv_bfloat162*>(&a),
                               *reinterpret_cast<__nv_bfloat162*>(&b));
    return *reinterpret_cast<unsigned*>(&r);
}

static __device__ __forceinline__ void mma16816(
    float& d0, float& d1, float& d2, float& d3,
    unsigned a0, unsigned a1, unsigned a2, unsigned a3,
    unsigned b0, unsigned b1)
{
    asm volatile(
      "mma.sync.aligned.m16n8k16.row.col.f32.bf16.bf16.f32 "
      "{%0,%1,%2,%3}, {%4,%5,%6,%7}, {%8,%9}, {%0,%1,%2,%3};"
      : "+f"(d0), "+f"(d1), "+f"(d2), "+f"(d3)
      : "r"(a0), "r"(a1), "r"(a2), "r"(a3), "r"(b0), "r"(b1));
}

// gelu(a) ~= 0.5*a*(1 + tanh(0.851*a))  (== a*sigmoid(1.702a), single MUFU)
static __device__ __forceinline__ float gelu_fast(float a) {
    float ta;
    asm("tanh.approx.f32 %0, %1;" : "=f"(ta) : "f"(0.851f * a));
    float b = 0.5f * a;
    return fmaf(b, ta, b);
}

// ---------------------------------------------------------------------------
// Kernel 1: prep — convert x to bf16 and zero x1h. Exact-cover grid, 5
// strided elements per thread, loads batched first (MLP=5).
// ---------------------------------------------------------------------------
__global__ void __launch_bounds__(256) prep_kernel(const float4* __restrict__ x4) {
    const int tid = blockIdx.x * blockDim.x + threadIdx.x;
    uint2* xh2 = reinterpret_cast<uint2*>(g_xh);
    uint2* x12 = reinterpret_cast<uint2*>(g_x1h);
    float4 v[PREP_PER_THREAD];
#pragma unroll
    for (int k = 0; k < PREP_PER_THREAD; k++)
        v[k] = x4[tid + k * PREP_THREADS];
#pragma unroll
    for (int k = 0; k < PREP_PER_THREAD; k++) {
        int i = tid + k * PREP_THREADS;
        xh2[i] = make_uint2(pk(v[k].x, v[k].y), pk(v[k].z, v[k].w));
        x12[i] = make_uint2(0u, 0u);
    }
}

// ---------------------------------------------------------------------------
// Kernel 2: edge pass (R10/R8 design — best measured). One warp = 32 edges/
// iter (2 HMMA tiles), batched loads; scatter balanced across all 32 lanes.
// sigma: D pair of group nt, lane t -> ch (nt>>1)*16 + 4t (+2 if nt odd).
// ---------------------------------------------------------------------------
__global__ void __launch_bounds__(256, 2) edge_kernel(
    const float* __restrict__ basis,
    const int* __restrict__ eidx,
    const float* __restrict__ W)
{
    const int lane = threadIdx.x & 31;
    const int t = lane & 3, g = lane >> 2;
    const int gwarp = (int)((blockIdx.x * blockDim.x + threadIdx.x) >> 5);
    const int nwarp = (int)((gridDim.x * blockDim.x) >> 5);

    unsigned bw[2][8][2];
#pragma unroll
    for (int kt = 0; kt < 2; kt++)
#pragma unroll
        for (int nt = 0; nt < 8; nt++) {
            int ch = (nt >> 1) * 16 + ((g >> 1) << 2) + (g & 1) + ((nt & 1) << 1);
            int col = kt * 16 + 2 * t;
            float2 p0 = *reinterpret_cast<const float2*>(W + ch * KD + col);
            float2 p1 = *reinterpret_cast<const float2*>(W + ch * KD + col + 8);
            bw[kt][nt][0] = pk(p0.x, p0.y);
            bw[kt][nt][1] = pk(p1.x, p1.y);
        }

    const uint2* xh2 = reinterpret_cast<const uint2*>(g_xh);
    const int NI = EE / 32;
    for (int it = gwarp; it < NI; it += nwarp) {
        const int e0 = it * 32;
        const int r0a = e0 + g,      r1a = e0 + 8 + g;
        const int r0b = e0 + 16 + g, r1b = e0 + 24 + g;
        const int s0a = __ldg(eidx + r0a), s1a = __ldg(eidx + r1a);
        const int s0b = __ldg(eidx + r0b), s1b = __ldg(eidx + r1b);
        const int d0a = __ldg(eidx + EE + r0a), d1a = __ldg(eidx + EE + r1a);
        const int d0b = __ldg(eidx + EE + r0b), d1b = __ldg(eidx + EE + r1b);

        unsigned Aa[2][4], Ab[2][4];
#pragma unroll
        for (int kt = 0; kt < 2; kt++) {
            const int cb = kt * 16 + 2 * t;
            float2 qa0 = *reinterpret_cast<const float2*>(basis + (size_t)r0a * KD + cb);
            float2 qa1 = *reinterpret_cast<const float2*>(basis + (size_t)r1a * KD + cb);
            float2 qa2 = *reinterpret_cast<const float2*>(basis + (size_t)r0a * KD + cb + 8);
            float2 qa3 = *reinterpret_cast<const float2*>(basis + (size_t)r1a * KD + cb + 8);
            float2 qb0 = *reinterpret_cast<const float2*>(basis + (size_t)r0b * KD + cb);
            float2 qb1 = *reinterpret_cast<const float2*>(basis + (size_t)r1b * KD + cb);
            float2 qb2 = *reinterpret_cast<const float2*>(basis + (size_t)r0b * KD + cb + 8);
            float2 qb3 = *reinterpret_cast<const float2*>(basis + (size_t)r1b * KD + cb + 8);
            Aa[kt][0] = pk(qa0.x, qa0.y); Aa[kt][1] = pk(qa1.x, qa1.y);
            Aa[kt][2] = pk(qa2.x, qa2.y); Aa[kt][3] = pk(qa3.x, qa3.y);
            Ab[kt][0] = pk(qb0.x, qb0.y); Ab[kt][1] = pk(qb1.x, qb1.y);
            Ab[kt][2] = pk(qb2.x, qb2.y); Ab[kt][3] = pk(qb3.x, qb3.y);
        }

        uint2 va0[4], va1[4], vb0[4], vb1[4];
#pragma unroll
        for (int ntp = 0; ntp < 4; ntp++) {
            va0[ntp] = xh2[(size_t)s0a * 16 + ntp * 4 + t];
            va1[ntp] = xh2[(size_t)s1a * 16 + ntp * 4 + t];
            vb0[ntp] = xh2[(size_t)s0b * 16 + ntp * 4 + t];
            vb1[ntp] = xh2[(size_t)s1b * 16 + ntp * 4 + t];
        }

#pragma unroll
        for (int tile = 0; tile < 2; tile++) {
            const unsigned (*A)[4] = tile ? Ab : Aa;
            const uint2* v0 = tile ? vb0 : va0;
            const uint2* v1 = tile ? vb1 : va1;
            const int dd0 = tile ? d0b : d0a;
            const int dd1 = tile ? d1b : d1a;
#pragma unroll
            for (int ntp = 0; ntp < 4; ntp++) {
                const int nt0 = 2 * ntp, nt1 = nt0 + 1;
                float D0[4] = {0.f, 0.f, 0.f, 0.f};
                float D1[4] = {0.f, 0.f, 0.f, 0.f};
#pragma unroll
                for (int kt = 0; kt < 2; kt++) {
                    mma16816(D0[0], D0[1], D0[2], D0[3],
                             A[kt][0], A[kt][1], A[kt][2], A[kt][3],
                             bw[kt][nt0][0], bw[kt][nt0][1]);
                    mma16816(D1[0], D1[1], D1[2], D1[3],
                             A[kt][0], A[kt][1], A[kt][2], A[kt][3],
                             bw[kt][nt1][0], bw[kt][nt1][1]);
                }
                unsigned q0x = hm2(pk(D0[0], D0[1]), v0[ntp].x);
                unsigned q0y = hm2(pk(D1[0], D1[1]), v0[ntp].y);
                unsigned q1x = hm2(pk(D0[2], D0[3]), v1[ntp].x);
                unsigned q1y = hm2(pk(D1[2], D1[3]), v1[ntp].y);
                unsigned p0x = __shfl_xor_sync(0xffffffffu, q0x, 1);
                unsigned p0y = __shfl_xor_sync(0xffffffffu, q0y, 1);
                unsigned p1x = __shfl_xor_sync(0xffffffffu, q1x, 1);
                unsigned p1y = __shfl_xor_sync(0xffffffffu, q1y, 1);
                if (!(t & 1)) {
                    __nv_bfloat16* a0 = g_x1h + (size_t)dd0 * CC + ntp * 16 + 4 * t;
                    asm volatile("red.global.add.noftz.v4.bf16x2 [%0], {%1,%2,%3,%4};"
                                 :: "l"(a0), "r"(q0x), "r"(q0y), "r"(p0x), "r"(p0y) : "memory");
                } else {
                    __nv_bfloat16* a1 = g_x1h + (size_t)dd1 * CC + ntp * 16 + 4 * (t - 1);
                    asm volatile("red.global.add.noftz.v4.bf16x2 [%0], {%1,%2,%3,%4};"
                                 :: "l"(a1), "r"(p1x), "r"(p1y), "r"(q1x), "r"(q1y) : "memory");
                }
            }
        }
    }
}

// ---------------------------------------------------------------------------
// Kernel 3: fused LN -> Lin(64->256) -> GELU -> Lin(256->64) -> ls*h + x.
// (R16 code; GELU now single-MUFU tanh.approx form)
// ---------------------------------------------------------------------------
__global__ void __launch_bounds__(256, 2) mlp_kernel(
    const float* __restrict__ x,
    const float* __restrict__ cbias,
    const float* __restrict__ gamma_,
    const float* __restrict__ beta_,
    const float* __restrict__ W1,
    const float* __restrict__ b1,
    const float* __restrict__ W2,
    const float* __restrict__ b2,
    const float* __restrict__ lscale,
    float* __restrict__ out)
{
    extern __shared__ unsigned char smraw[];
    uint2*  w1f = reinterpret_cast<uint2*>(smraw);
    uint2*  w2f = w1f + 4096;
    float2* b1p = reinterpret_cast<float2*>(w2f + 4096);
    float4* cbp4 = reinterpret_cast<float4*>(b1p + 1024);
    float4* gp4  = cbp4 + 128;
    float4* bp4  = gp4 + 128;
    float2* lsp = reinterpret_cast<float2*>(bp4 + 128);
    float2* lb2 = lsp + 256;

    const int tid = threadIdx.x;
    for (int i = tid; i < 4096; i += 256) {
        int kt = i >> 10, rem = i & 1023, ntg = rem >> 5, ln = rem & 31;
        int tt = ln & 3, gq = ln >> 2;
        int j = ntg * 8 + gq;
        float4 w = *reinterpret_cast<const float4*>(W1 + j * CC + kt * 16 + 4 * tt);
        w1f[i] = make_uint2(pk(w.x, w.y), pk(w.z, w.w));
    }
    for (int i = tid; i < 4096; i += 256) {
        int kt = i >> 8, rem = i & 255, nt = rem >> 5, ln = rem & 31;
        int tt = ln & 3, gq = ln >> 2;
        int c = nt * 8 + gq;
        int j = kt * 16 + 2 * tt;
        float2 p0 = *reinterpret_cast<const float2*>(W2 + c * HH + j);
        float2 p1 = *reinterpret_cast<const float2*>(W2 + c * HH + j + 8);
        w2f[i] = make_uint2(pk(p0.x, p0.y), pk(p1.x, p1.y));
    }
    for (int i = tid; i < 1024; i += 256) {
        int ch = i >> 8, rem = i & 255, nt = rem >> 5, ln = rem & 31, tt = ln & 3;
        int j = ch * 64 + nt * 8 + 2 * tt;
        b1p[i] = make_float2(b1[j], b1[j + 1]);
    }
    if (tid < 128) {
        int kt = tid >> 5, ln = tid & 31, tt = ln & 3;
        int c = kt * 16 + 4 * tt;
        cbp4[tid] = *reinterpret_cast<const float4*>(cbias + c);
        gp4[tid]  = *reinterpret_cast<const float4*>(gamma_ + c);
        bp4[tid]  = *reinterpret_cast<const float4*>(beta_ + c);
    }
    for (int i = tid; i < 256; i += 256) {
        int u = i >> 5, ln = i & 31, tt = ln & 3;
        int c = u * 8 + 2 * tt;
        float2 ls = *reinterpret_cast<const float2*>(lscale + c);
        float2 bb = *reinterpret_cast<const float2*>(b2 + c);
        lsp[i] = ls;
        lb2[i] = make_float2(ls.x * bb.x, ls.y * bb.y);
    }
    __syncthreads();

    const int lane = tid & 31, t = lane & 3, gq = lane >> 2;
    const int gwarp = (int)((blockIdx.x * 256 + tid) >> 5);
    const int nwarp = (int)(gridDim.x * 8);
    const uint2* x1h2 = reinterpret_cast<const uint2*>(g_x1h);
    const float2* xf2 = reinterpret_cast<const float2*>(x);
    float2* of2 = reinterpret_cast<float2*>(out);

    for (int grp = gwarp; grp < NN / 16; grp += nwarp) {
        const int row0 = grp * 16 + gq, row1 = row0 + 8;

        float a0[16], a1[16];
        float s0 = 0.f, q0 = 0.f, s1 = 0.f, q1 = 0.f;
#pragma unroll
        for (int kt = 0; kt < 4; kt++) {
            uint2 u0 = x1h2[(size_t)row0 * 16 + kt * 4 + t];
            uint2 u1 = x1h2[(size_t)row1 * 16 + kt * 4 + t];
            float4 cb = cbp4[kt * 32 + lane];
            float2 l0 = __bfloat1622float2(*reinterpret_cast<__nv_bfloat162*>(&u0.x));
            float2 h0 = __bfloat1622float2(*reinterpret_cast<__nv_bfloat162*>(&u0.y));
            float2 l1 = __bfloat1622float2(*reinterpret_cast<__nv_bfloat162*>(&u1.x));
            float2 h1 = __bfloat1622float2(*reinterpret_cast<__nv_bfloat162*>(&u1.y));
            a0[kt*4+0] = l0.x + cb.x; a0[kt*4+1] = l0.y + cb.y;
            a0[kt*4+2] = h0.x + cb.z; a0[kt*4+3] = h0.y + cb.w;
            a1[kt*4+0] = l1.x + cb.x; a1[kt*4+1] = l1.y + cb.y;
            a1[kt*4+2] = h1.x + cb.z; a1[kt*4+3] = h1.y + cb.w;
#pragma unroll
            for (int u = 0; u < 4; u++) {
                s0 += a0[kt*4+u]; q0 += a0[kt*4+u] * a0[kt*4+u];
                s1 += a1[kt*4+u]; q1 += a1[kt*4+u] * a1[kt*4+u];
            }
        }
#pragma unroll
        for (int o = 1; o <= 2; o <<= 1) {
            s0 += __shfl_xor_sync(0xffffffffu, s0, o);
            q0 += __shfl_xor_sync(0xffffffffu, q0, o);
            s1 += __shfl_xor_sync(0xffffffffu, s1, o);
            q1 += __shfl_xor_sync(0xffffffffu, q1, o);
        }
        float mu0 = s0 * (1.f / CC), mu1 = s1 * (1.f / CC);
        float rs0 = rsqrtf(q0 * (1.f / CC) - mu0 * mu0 + 1e-5f);
        float rs1 = rsqrtf(q1 * (1.f / CC) - mu1 * mu1 + 1e-5f);

        unsigned Afr[4][4];
#pragma unroll
        for (int kt = 0; kt < 4; kt++) {
            float4 gg = gp4[kt * 32 + lane], be = bp4[kt * 32 + lane];
            float n00 = (a0[kt*4+0] - mu0) * rs0 * gg.x + be.x;
            float n01 = (a0[kt*4+1] - mu0) * rs0 * gg.y + be.y;
            float n02 = (a0[kt*4+2] - mu0) * rs0 * gg.z + be.z;
            float n03 = (a0[kt*4+3] - mu0) * rs0 * gg.w + be.w;
            float n10 = (a1[kt*4+0] - mu1) * rs1 * gg.x + be.x;
            float n11 = (a1[kt*4+1] - mu1) * rs1 * gg.y + be.y;
            float n12 = (a1[kt*4+2] - mu1) * rs1 * gg.z + be.z;
            float n13 = (a1[kt*4+3] - mu1) * rs1 * gg.w + be.w;
            Afr[kt][0] = pk(n00, n01);
            Afr[kt][1] = pk(n10, n11);
            Afr[kt][2] = pk(n02, n03);
            Afr[kt][3] = pk(n12, n13);
        }

        float O[8][4];
#pragma unroll
        for (int nt = 0; nt < 8; nt++) { O[nt][0]=0.f; O[nt][1]=0.f; O[nt][2]=0.f; O[nt][3]=0.f; }

#pragma unroll
        for (int ch = 0; ch < 4; ch++) {
            float D1[8][4];
#pragma unroll
            for (int nt = 0; nt < 8; nt++) {
                float2 bb = b1p[(ch * 8 + nt) * 32 + lane];
                D1[nt][0] = bb.x; D1[nt][1] = bb.y; D1[nt][2] = bb.x; D1[nt][3] = bb.y;
            }
#pragma unroll
            for (int kt = 0; kt < 4; kt++) {
#pragma unroll
                for (int nt = 0; nt < 8; nt++) {
                    uint2 b = w1f[(kt * 32 + ch * 8 + nt) * 32 + lane];
                    mma16816(D1[nt][0], D1[nt][1], D1[nt][2], D1[nt][3],
                             Afr[kt][0], Afr[kt][1], Afr[kt][2], Afr[kt][3], b.x, b.y);
                }
            }
            // GELU (tanh.approx form — error suppressed by layer_scale)
#pragma unroll
            for (int nt = 0; nt < 8; nt++)
#pragma unroll
                for (int r = 0; r < 4; r++)
                    D1[nt][r] = gelu_fast(D1[nt][r]);
            unsigned Ap[4][4];
#pragma unroll
            for (int k2 = 0; k2 < 4; k2++) {
                Ap[k2][0] = pk(D1[2 * k2][0],     D1[2 * k2][1]);
                Ap[k2][1] = pk(D1[2 * k2][2],     D1[2 * k2][3]);
                Ap[k2][2] = pk(D1[2 * k2 + 1][0], D1[2 * k2 + 1][1]);
                Ap[k2][3] = pk(D1[2 * k2 + 1][2], D1[2 * k2 + 1][3]);
            }
#pragma unroll
            for (int k2 = 0; k2 < 4; k2++) {
                int ktg = ch * 4 + k2;
#pragma unroll
                for (int nt = 0; nt < 8; nt++) {
                    uint2 b = w2f[(ktg * 8 + nt) * 32 + lane];
                    mma16816(O[nt][0], O[nt][1], O[nt][2], O[nt][3],
                             Ap[k2][0], Ap[k2][1], Ap[k2][2], Ap[k2][3], b.x, b.y);
                }
            }
        }

#pragma unroll
        for (int nt = 0; nt < 8; nt++) {
            float2 ls = lsp[nt * 32 + lane];
            float2 lb = lb2[nt * 32 + lane];
            float2 xa = xf2[(size_t)row0 * 32 + nt * 4 + t];
            float2 xb = xf2[(size_t)row1 * 32 + nt * 4 + t];
            float2 ra, rb;
            ra.x = xa.x + lb.x + ls.x * O[nt][0];
            ra.y = xa.y + lb.y + ls.y * O[nt][1];
            rb.x = xb.x + lb.x + ls.x * O[nt][2];
            rb.y = xb.y + lb.y + ls.y * O[nt][3];
            of2[(size_t)row0 * 32 + nt * 4 + t] = ra;
            of2[(size_t)row1 * 32 + nt * 4 + t] = rb;
        }
    }
}

// ---------------------------------------------------------------------------
// launch  (inputs: 0 x, 1 kernel_basis, 2 fiber_kernel_basis, 3 edge_index
// (int32), 4 kernel_W, 5 conv_bias, 6 ln_gamma, 7 ln_beta, 8 W1, 9 b1,
// 10 W2, 11 b2, 12 layer_scale)
// ---------------------------------------------------------------------------
extern "C" void kernel_launch(void* const* d_in, const int* in_sizes, int n_in,
                              void* d_out, int out_size) {
    const float* x      = (const float*)d_in[0];
    const float* basis  = (const float*)d_in[1];
    const int*   eidx   = (const int*)d_in[3];
    const float* W      = (const float*)d_in[4];
    const float* cbias  = (const float*)d_in[5];
    const float* gamma_ = (const float*)d_in[6];
    const float* beta_  = (const float*)d_in[7];
    const float* W1     = (const float*)d_in[8];
    const float* b1     = (const float*)d_in[9];
    const float* W2     = (const float*)d_in[10];
    const float* b2     = (const float*)d_in[11];
    const float* lsc    = (const float*)d_in[12];
    float*       out    = (float*)d_out;

    prep_kernel<<<1250, 256>>>((const float4*)x);
    edge_kernel<<<592, 256>>>(basis, eidx, W);

    const int smem = 32768 + 32768 + 8192 + 3 * 2048 + 2 * 2048;  // 83968 B
    cudaFuncSetAttribute(mlp_kernel, cudaFuncAttributeMaxDynamicSharedMemorySize, smem);
    mlp_kernel<<<296, 256, smem>>>(x, cbias, gamma_, beta_, W1, b1, W2, b2, lsc, out);
}